// round 11
// baseline (speedup 1.0000x reference)
#include <cuda_runtime.h>
#include <stdint.h>

// NeighborNoiser — partitionable threefry2x32, key (0,42), fold = x0^x1 (bit-exact R2+).
// R11: front-end experiment. Same work/mix as R10 (4px/thread, 1 wide : 3 SHF chains)
// but as a #pragma unroll 1 loop, 1 px/iteration — body ~4.7KB fits L0 I$ (6KB).
// Hypothesis: the 0.757 issue pin is straight-line instruction-fetch bound; a warm
// L0 loop body lifts it. Slots +~3.5% (loop ctrl + scalar loads); memory is at 8%.

#define N1 25165824u                    // 8*3*1024*1024

__device__ __forceinline__ uint32_t rotl(uint32_t v, const int d) {
    return __funnelshift_l(v, v, d);
}

#define RS(d) { x0 += x1; x1 = rotl(x1,(d)) ^ x0; }

// SHF-rotate chain (alu-heavy)
__device__ __forceinline__ uint32_t tf_shf(uint32_t ctr) {
    const uint32_t ks1 = 42u, ks2 = 0x1BD11BDAu ^ 42u;
    uint32_t x1 = ctr + ks1;
    uint32_t x0 = x1;                               // round-1 add with x0 = 0
    x1 = rotl(x1,13) ^ x0;
    RS(15) RS(26) RS(6)
    x1 += ks2 + 1u;  x0 = x0 + x1 + ks1;  x1 = rotl(x1,17) ^ x0;   // IADD3 fuse
    RS(29) RS(16) RS(24)
    x1 += 2u;        x0 = x0 + x1 + ks2;  x1 = rotl(x1,13) ^ x0;
    RS(15) RS(26) RS(6)
    x1 += ks1 + 3u;  x0 = x0 + x1;        x1 = rotl(x1,17) ^ x0;   // ks0 = 0
    RS(29) RS(16) RS(24)
    x1 += ks2 + 4u;  x0 = x0 + x1 + ks1;  x1 = rotl(x1,13) ^ x0;
    RS(15) RS(26) RS(6)
    x1 += 5u;
    return (x0 + ks2) ^ x1;
}

// wide-mul rotate: IMAD.WIDE (fma pipe) + single LOP3 ((lo|hi)^x0)
__device__ __forceinline__ uint32_t wrot(uint32_t v, uint32_t pw) {
    uint32_t lo, hi;
    asm("{\n\t.reg .b64 w;\n\tmul.wide.u32 w, %2, %3;\n\tmov.b64 {%0, %1}, w;\n\t}"
        : "=r"(lo), "=r"(hi) : "r"(v), "r"(pw));
    return lo | hi;
}

#define RW(p) { x0 += x1; x1 = wrot(x1,(p)) ^ x0; }

__device__ __forceinline__ uint32_t tf_wide(uint32_t ctr) {
    const uint32_t ks1 = 42u, ks2 = 0x1BD11BDAu ^ 42u;
    const uint32_t p13 = 1u<<13, p15 = 1u<<15, p26 = 1u<<26, p6 = 1u<<6;
    const uint32_t p17 = 1u<<17, p29 = 1u<<29, p16 = 1u<<16, p24 = 1u<<24;
    uint32_t x1 = ctr + ks1;
    uint32_t x0 = x1;
    x1 = wrot(x1,p13) ^ x0;
    RW(p15) RW(p26) RW(p6)
    x1 += ks2 + 1u;  x0 = x0 + x1 + ks1;  x1 = wrot(x1,p17) ^ x0;
    RW(p29) RW(p16) RW(p24)
    x1 += 2u;        x0 = x0 + x1 + ks2;  x1 = wrot(x1,p13) ^ x0;
    RW(p15) RW(p26) RW(p6)
    x1 += ks1 + 3u;  x0 = x0 + x1;        x1 = wrot(x1,p17) ^ x0;
    RW(p29) RW(p16) RW(p24)
    x1 += ks2 + 4u;  x0 = x0 + x1 + ks1;  x1 = wrot(x1,p13) ^ x0;
    RW(p15) RW(p26) RW(p6)
    x1 += 5u;
    return (x0 + ks2) ^ x1;
}

// Single IMAD.HI: hi(bits * 2^23) + 0x3f800000 -> float in [1,2); then -1.
__device__ __forceinline__ float u01(uint32_t bits) {
    uint32_t m;
    asm("mad.hi.u32 %0, %1, %2, %3;"
        : "=r"(m) : "r"(bits), "r"(1u << 23), "r"(0x3f800000u));
    return __uint_as_float(m) - 1.0f;
}

__global__ __launch_bounds__(256, 6)
void neighbor_noiser_kernel(const float* __restrict__ t, float* __restrict__ out) {
    uint32_t gid  = blockIdx.x * blockDim.x + threadIdx.x;
    uint32_t base = gid * 4u;                   // 4 adjacent pixels in one row

    uint32_t plane = base >> 20;
    uint32_t pos   = base & 0xFFFFFu;
    uint32_t y     = pos >> 10;
    uint32_t x     = pos & 1023u;               // multiple of 4

    const float* p = t + ((size_t)plane << 20);
    uint32_t yu = (y == 0u)    ? 0u    : y - 1u;
    uint32_t yd = (y == 1023u) ? 1023u : y + 1u;
    const float* rowc = p + (y  << 10);
    const float* rowu = p + (yu << 10);
    const float* rowd = p + (yd << 10);

#pragma unroll 1
    for (uint32_t i = 0; i < 4u; ++i) {
        uint32_t xi = x + i;
        uint32_t j  = base + i;

        // loads first — consumed ~250 instructions later, latency fully hidden
        float up = __ldg(rowu + xi);
        float dn = __ldg(rowd + xi);
        uint32_t xl = (xi == 0u)    ? 0u    : xi - 1u;
        uint32_t xr = (xi == 1023u) ? 1023u : xi + 1u;
        float lf = __ldg(rowc + xl);
        float rt = __ldg(rowc + xr);

        // 4 independent chains: up-chain wide (fma rotate), other 3 SHF
        uint32_t bu = tf_wide(j);
        uint32_t bd = tf_shf(j + N1);
        uint32_t bl = tf_shf(j + 2u * N1);
        uint32_t br = tf_shf(j + 3u * N1);

        float ur = u01(bu);
        float dr = u01(bd);
        float lr = u01(bl);
        float rr = u01(br);

        float s   = (ur + dr) + (lr + rr);
        float num = fmaf(up, ur, fmaf(dn, dr, fmaf(lf, lr, rt * rr)));
        out[j] = __fdividef(num, s);
    }
}

extern "C" void kernel_launch(void* const* d_in, const int* in_sizes, int n_in,
                              void* d_out, int out_size) {
    const float* t = (const float*)d_in[0];
    float* out = (float*)d_out;
    (void)in_sizes; (void)n_in; (void)out_size;

    const uint32_t threads = 256;
    const uint32_t blocks = (N1 / 4u) / threads;   // 24576, exact
    neighbor_noiser_kernel<<<blocks, threads>>>(t, out);
}

// round 12
// speedup vs baseline: 1.0377x; 1.0377x over previous
#include <cuda_runtime.h>
#include <stdint.h>

// NeighborNoiser — partitionable threefry2x32, key (0,42), fold = x0^x1 (bit-exact R2+).
// R12: the untested cell — 4 px/thread with 2 wide : 2 SHF chains per pixel AT
// ~70% occupancy (launch_bounds(256,6) caps regs at 42; R8's 2:2 attempt died at
// 46 regs / 59.8% occ). Slot count matches R10 (~191 slot-us). Discriminates:
// alu-share-dependent issue pin (-> ~240us) vs universal 0.75 pin (-> ~255us).

#define N1 25165824u                    // 8*3*1024*1024

__device__ __forceinline__ uint32_t rotl(uint32_t v, const int d) {
    return __funnelshift_l(v, v, d);
}

#define RS(d) { x0 += x1; x1 = rotl(x1,(d)) ^ x0; }

// SHF-rotate chain (alu-heavy)
__device__ __forceinline__ uint32_t tf_shf(uint32_t ctr) {
    const uint32_t ks1 = 42u, ks2 = 0x1BD11BDAu ^ 42u;
    uint32_t x1 = ctr + ks1;
    uint32_t x0 = x1;                               // round-1 add with x0 = 0
    x1 = rotl(x1,13) ^ x0;
    RS(15) RS(26) RS(6)
    x1 += ks2 + 1u;  x0 = x0 + x1 + ks1;  x1 = rotl(x1,17) ^ x0;   // IADD3 fuse
    RS(29) RS(16) RS(24)
    x1 += 2u;        x0 = x0 + x1 + ks2;  x1 = rotl(x1,13) ^ x0;
    RS(15) RS(26) RS(6)
    x1 += ks1 + 3u;  x0 = x0 + x1;        x1 = rotl(x1,17) ^ x0;   // ks0 = 0
    RS(29) RS(16) RS(24)
    x1 += ks2 + 4u;  x0 = x0 + x1 + ks1;  x1 = rotl(x1,13) ^ x0;
    RS(15) RS(26) RS(6)
    x1 += 5u;
    return (x0 + ks2) ^ x1;
}

// wide-mul rotate: IMAD.WIDE (fma pipe) + single LOP3 ((lo|hi)^x0)
__device__ __forceinline__ uint32_t wrot(uint32_t v, uint32_t pw) {
    uint32_t lo, hi;
    asm("{\n\t.reg .b64 w;\n\tmul.wide.u32 w, %2, %3;\n\tmov.b64 {%0, %1}, w;\n\t}"
        : "=r"(lo), "=r"(hi) : "r"(v), "r"(pw));
    return lo | hi;
}

#define RW(p) { x0 += x1; x1 = wrot(x1,(p)) ^ x0; }

__device__ __forceinline__ uint32_t tf_wide(uint32_t ctr) {
    const uint32_t ks1 = 42u, ks2 = 0x1BD11BDAu ^ 42u;
    const uint32_t p13 = 1u<<13, p15 = 1u<<15, p26 = 1u<<26, p6 = 1u<<6;
    const uint32_t p17 = 1u<<17, p29 = 1u<<29, p16 = 1u<<16, p24 = 1u<<24;
    uint32_t x1 = ctr + ks1;
    uint32_t x0 = x1;
    x1 = wrot(x1,p13) ^ x0;
    RW(p15) RW(p26) RW(p6)
    x1 += ks2 + 1u;  x0 = x0 + x1 + ks1;  x1 = wrot(x1,p17) ^ x0;
    RW(p29) RW(p16) RW(p24)
    x1 += 2u;        x0 = x0 + x1 + ks2;  x1 = wrot(x1,p13) ^ x0;
    RW(p15) RW(p26) RW(p6)
    x1 += ks1 + 3u;  x0 = x0 + x1;        x1 = wrot(x1,p17) ^ x0;
    RW(p29) RW(p16) RW(p24)
    x1 += ks2 + 4u;  x0 = x0 + x1 + ks1;  x1 = wrot(x1,p13) ^ x0;
    RW(p15) RW(p26) RW(p6)
    x1 += 5u;
    return (x0 + ks2) ^ x1;
}

// Single IMAD.HI: hi(bits * 2^23) + 0x3f800000 -> float in [1,2); then -1.
__device__ __forceinline__ float u01(uint32_t bits) {
    uint32_t m;
    asm("mad.hi.u32 %0, %1, %2, %3;"
        : "=r"(m) : "r"(bits), "r"(1u << 23), "r"(0x3f800000u));
    return __uint_as_float(m) - 1.0f;
}

__global__ __launch_bounds__(256, 6)
void neighbor_noiser_kernel(const float* __restrict__ t, float* __restrict__ out) {
    uint32_t gid  = blockIdx.x * blockDim.x + threadIdx.x;
    uint32_t base = gid * 4u;                   // 4 adjacent pixels in one row

    uint32_t plane = base >> 20;
    uint32_t pos   = base & 0xFFFFFu;
    uint32_t y     = pos >> 10;
    uint32_t x     = pos & 1023u;               // multiple of 4

    const float* p = t + ((size_t)plane << 20);
    uint32_t yu = (y == 0u)    ? 0u    : y - 1u;
    uint32_t yd = (y == 1023u) ? 1023u : y + 1u;
    const float* rowc = p + (y << 10);

    float4 up4 = __ldg((const float4*)(p + (yu << 10) + x));
    float4 dn4 = __ldg((const float4*)(p + (yd << 10) + x));
    float4 ct4 = __ldg((const float4*)(rowc + x));
    float lf_e = (x == 0u)     ? ct4.x : __ldg(rowc + x - 1u);
    float rt_e = (x == 1020u)  ? ct4.w : __ldg(rowc + x + 4u);

    // 16 chains: per pixel, up+down wide (fma rotate), left+right SHF (alu rotate)
    uint32_t bu0 = tf_wide(base);
    uint32_t bu1 = tf_wide(base + 1u);
    uint32_t bu2 = tf_wide(base + 2u);
    uint32_t bu3 = tf_wide(base + 3u);
    uint32_t bd0 = tf_wide(base + N1);
    uint32_t bd1 = tf_wide(base + N1 + 1u);
    uint32_t bd2 = tf_wide(base + N1 + 2u);
    uint32_t bd3 = tf_wide(base + N1 + 3u);
    uint32_t bl0 = tf_shf(base + 2u*N1);
    uint32_t bl1 = tf_shf(base + 2u*N1 + 1u);
    uint32_t bl2 = tf_shf(base + 2u*N1 + 2u);
    uint32_t bl3 = tf_shf(base + 2u*N1 + 3u);
    uint32_t br0 = tf_shf(base + 3u*N1);
    uint32_t br1 = tf_shf(base + 3u*N1 + 1u);
    uint32_t br2 = tf_shf(base + 3u*N1 + 2u);
    uint32_t br3 = tf_shf(base + 3u*N1 + 3u);

    float upv[4] = {up4.x, up4.y, up4.z, up4.w};
    float dnv[4] = {dn4.x, dn4.y, dn4.z, dn4.w};
    float lfv[4] = {lf_e,  ct4.x, ct4.y, ct4.z};
    float rtv[4] = {ct4.y, ct4.z, ct4.w, rt_e};
    uint32_t buv[4] = {bu0, bu1, bu2, bu3};
    uint32_t bdv[4] = {bd0, bd1, bd2, bd3};
    uint32_t blv[4] = {bl0, bl1, bl2, bl3};
    uint32_t brv[4] = {br0, br1, br2, br3};

    float res[4];
#pragma unroll
    for (int i = 0; i < 4; i++) {
        float ur = u01(buv[i]);
        float dr = u01(bdv[i]);
        float lr = u01(blv[i]);
        float rr = u01(brv[i]);
        float s   = (ur + dr) + (lr + rr);
        float num = fmaf(upv[i], ur, fmaf(dnv[i], dr, fmaf(lfv[i], lr, rtv[i] * rr)));
        res[i] = __fdividef(num, s);
    }

    *reinterpret_cast<float4*>(out + base) = make_float4(res[0], res[1], res[2], res[3]);
}

extern "C" void kernel_launch(void* const* d_in, const int* in_sizes, int n_in,
                              void* d_out, int out_size) {
    const float* t = (const float*)d_in[0];
    float* out = (float*)d_out;
    (void)in_sizes; (void)n_in; (void)out_size;

    const uint32_t threads = 256;
    const uint32_t blocks = (N1 / 4u) / threads;   // 24576, exact
    neighbor_noiser_kernel<<<blocks, threads>>>(t, out);
}

// round 13
// speedup vs baseline: 1.0891x; 1.0495x over previous
#include <cuda_runtime.h>
#include <stdint.h>

// NeighborNoiser — partitionable threefry2x32, key (0,42), fold = x0^x1 (bit-exact R2+).
// R13: R10 skeleton (4px/thread, IADD3-fused key schedule, IMAD.HI u01, float4 IO)
// with ALL 4 chains on SHF rotates. Evidence: issue rises with alu share
// (0.769 pure-SHF > 0.757 1-wide > 0.739 2-wide) — IMAD.WIDE's 64-bit reg pairs
// cost issue slots. Slot count unchanged vs R10; only issue efficiency should move.

#define N1 25165824u                    // 8*3*1024*1024

__device__ __forceinline__ uint32_t rotl(uint32_t v, const int d) {
    return __funnelshift_l(v, v, d);
}

#define RS(d) { x0 += x1; x1 = rotl(x1,(d)) ^ x0; }

// SHF-rotate threefry chain, IADD3-fused key schedule
__device__ __forceinline__ uint32_t tf_shf(uint32_t ctr) {
    const uint32_t ks1 = 42u, ks2 = 0x1BD11BDAu ^ 42u;
    uint32_t x1 = ctr + ks1;
    uint32_t x0 = x1;                               // round-1 add with x0 = 0
    x1 = rotl(x1,13) ^ x0;
    RS(15) RS(26) RS(6)
    x1 += ks2 + 1u;  x0 = x0 + x1 + ks1;  x1 = rotl(x1,17) ^ x0;
    RS(29) RS(16) RS(24)
    x1 += 2u;        x0 = x0 + x1 + ks2;  x1 = rotl(x1,13) ^ x0;
    RS(15) RS(26) RS(6)
    x1 += ks1 + 3u;  x0 = x0 + x1;        x1 = rotl(x1,17) ^ x0;   // ks0 = 0
    RS(29) RS(16) RS(24)
    x1 += ks2 + 4u;  x0 = x0 + x1 + ks1;  x1 = rotl(x1,13) ^ x0;
    RS(15) RS(26) RS(6)
    x1 += 5u;
    return (x0 + ks2) ^ x1;
}

// Single IMAD.HI (fma pipe): hi(bits * 2^23) + 0x3f800000 -> [1,2); then -1.
__device__ __forceinline__ float u01(uint32_t bits) {
    uint32_t m;
    asm("mad.hi.u32 %0, %1, %2, %3;"
        : "=r"(m) : "r"(bits), "r"(1u << 23), "r"(0x3f800000u));
    return __uint_as_float(m) - 1.0f;
}

__global__ __launch_bounds__(256, 6)
void neighbor_noiser_kernel(const float* __restrict__ t, float* __restrict__ out) {
    uint32_t gid  = blockIdx.x * blockDim.x + threadIdx.x;
    uint32_t base = gid * 4u;                   // 4 adjacent pixels in one row

    uint32_t plane = base >> 20;
    uint32_t pos   = base & 0xFFFFFu;
    uint32_t y     = pos >> 10;
    uint32_t x     = pos & 1023u;               // multiple of 4

    const float* p = t + ((size_t)plane << 20);
    uint32_t yu = (y == 0u)    ? 0u    : y - 1u;
    uint32_t yd = (y == 1023u) ? 1023u : y + 1u;
    const float* rowc = p + (y << 10);

    float4 up4 = __ldg((const float4*)(p + (yu << 10) + x));
    float4 dn4 = __ldg((const float4*)(p + (yd << 10) + x));
    float4 ct4 = __ldg((const float4*)(rowc + x));
    float lf_e = (x == 0u)     ? ct4.x : __ldg(rowc + x - 1u);
    float rt_e = (x == 1020u)  ? ct4.w : __ldg(rowc + x + 4u);

    // 16 independent SHF chains
    uint32_t bu0 = tf_shf(base);
    uint32_t bu1 = tf_shf(base + 1u);
    uint32_t bu2 = tf_shf(base + 2u);
    uint32_t bu3 = tf_shf(base + 3u);
    uint32_t bd0 = tf_shf(base + N1);
    uint32_t bd1 = tf_shf(base + N1 + 1u);
    uint32_t bd2 = tf_shf(base + N1 + 2u);
    uint32_t bd3 = tf_shf(base + N1 + 3u);
    uint32_t bl0 = tf_shf(base + 2u*N1);
    uint32_t bl1 = tf_shf(base + 2u*N1 + 1u);
    uint32_t bl2 = tf_shf(base + 2u*N1 + 2u);
    uint32_t bl3 = tf_shf(base + 2u*N1 + 3u);
    uint32_t br0 = tf_shf(base + 3u*N1);
    uint32_t br1 = tf_shf(base + 3u*N1 + 1u);
    uint32_t br2 = tf_shf(base + 3u*N1 + 2u);
    uint32_t br3 = tf_shf(base + 3u*N1 + 3u);

    float upv[4] = {up4.x, up4.y, up4.z, up4.w};
    float dnv[4] = {dn4.x, dn4.y, dn4.z, dn4.w};
    float lfv[4] = {lf_e,  ct4.x, ct4.y, ct4.z};
    float rtv[4] = {ct4.y, ct4.z, ct4.w, rt_e};
    uint32_t buv[4] = {bu0, bu1, bu2, bu3};
    uint32_t bdv[4] = {bd0, bd1, bd2, bd3};
    uint32_t blv[4] = {bl0, bl1, bl2, bl3};
    uint32_t brv[4] = {br0, br1, br2, br3};

    float res[4];
#pragma unroll
    for (int i = 0; i < 4; i++) {
        float ur = u01(buv[i]);
        float dr = u01(bdv[i]);
        float lr = u01(blv[i]);
        float rr = u01(brv[i]);
        float s   = (ur + dr) + (lr + rr);
        float num = fmaf(upv[i], ur, fmaf(dnv[i], dr, fmaf(lfv[i], lr, rtv[i] * rr)));
        res[i] = __fdividef(num, s);
    }

    *reinterpret_cast<float4*>(out + base) = make_float4(res[0], res[1], res[2], res[3]);
}

extern "C" void kernel_launch(void* const* d_in, const int* in_sizes, int n_in,
                              void* d_out, int out_size) {
    const float* t = (const float*)d_in[0];
    float* out = (float*)d_out;
    (void)in_sizes; (void)n_in; (void)out_size;

    const uint32_t threads = 256;
    const uint32_t blocks = (N1 / 4u) / threads;   // 24576, exact
    neighbor_noiser_kernel<<<blocks, threads>>>(t, out);
}